// round 5
// baseline (speedup 1.0000x reference)
#include <cuda_runtime.h>

// Problem constants (fixed shapes from reference)
#define NB_   512
#define B_    32
#define QH_   32
#define KVH_  8
#define G_    4          // GQA group: QH/KVH
#define D_    128
#define BS_   128
#define SCALE_ 0.08838834764831845f
#define CONSTV_ 10.0f
#define EPS_  1.1754943508222875e-38f

static __device__ float g_seqsum[B_ * QH_];   // per (batch, q-head) exp-sum accumulator

// ---- packed f32x2 helpers (Blackwell FFMA2 path) ----
__device__ __forceinline__ unsigned long long ffma2(unsigned long long a, unsigned long long b, unsigned long long c) {
    unsigned long long d;
    asm("fma.rn.f32x2 %0, %1, %2, %3;" : "=l"(d) : "l"(a), "l"(b), "l"(c));
    return d;
}
__device__ __forceinline__ unsigned long long fadd2(unsigned long long a, unsigned long long b) {
    unsigned long long d;
    asm("add.rn.f32x2 %0, %1, %2;" : "=l"(d) : "l"(a), "l"(b));
    return d;
}
__device__ __forceinline__ unsigned long long fpack2(float lo, float hi) {
    unsigned long long r;
    asm("mov.b64 %0, {%1, %2};" : "=l"(r) : "f"(lo), "f"(hi));
    return r;
}
__device__ __forceinline__ float2 funpack2(unsigned long long v) {
    float lo, hi;
    asm("mov.b64 {%0, %1}, %2;" : "=f"(lo), "=f"(hi) : "l"(v));
    return make_float2(lo, hi);
}

// ---- init: zero output + seq-sum scratch (d_out is poisoned by harness) ----
__global__ void pa_init(float* __restrict__ out) {
    int i = blockIdx.x * 256 + threadIdx.x;     // grid 512 x 256 == 131072 exactly
    out[i] = 0.0f;
    if (i < B_ * QH_) g_seqsum[i] = 0.0f;
}

// ---- main: one CTA per (block n, kv head). 128 threads. ----
__global__ void __launch_bounds__(128) pa_main(
    const float* __restrict__ query,        // [B, QH, D]
    const float* __restrict__ kcache,       // [NCB, BS, KVH, D]
    const float* __restrict__ vcache,       // [NCB, BS, KVH, D]
    const float* __restrict__ mapping,      // [NB, B] one-hot
    const float* __restrict__ bias,         // [NB, BS]
    const int*   __restrict__ blist,        // [NB]
    float* __restrict__ out)                // [B, QH, D]
{
    __shared__ float sm_q[G_ * D_];                 // scaled q, 4 heads (contiguous block of query)
    __shared__ float sm_bias[BS_];
    __shared__ unsigned long long sm_pp[G_ * BS_];  // exp(p) duplicated as (p,p) f32x2
    __shared__ unsigned long long sm_red[2048];     // 16KB scratch (QK: 8KB float view; PV: 16KB u64)
    __shared__ int   sm_b;
    __shared__ float sm_m;

    const int t  = threadIdx.x;
    const int n  = blockIdx.x >> 3;
    const int kv = blockIdx.x & 7;

    // find batch index from one-hot mapping row (warp 0)
    if (t < 32) {
        float m = mapping[n * B_ + t];
        unsigned msk = __ballot_sync(0xffffffffu, m > 0.5f);
        int bb = __ffs(msk) - 1;
        float mv = __shfl_sync(0xffffffffu, m, bb);
        if (t == 0) { sm_b = bb; sm_m = mv; }
    }
    __syncthreads();
    const int   b    = sm_b;
    const float mval = sm_m;
    const int   phys = blist[n];

    // stage scaled q (4 heads contiguous: query[b, kv*4 .. kv*4+3, :] = 512 floats) + bias
    {
        const float qs = SCALE_ * mval;
        const float* qsrc = query + (size_t)b * QH_ * D_ + (size_t)kv * G_ * D_;
        #pragma unroll
        for (int i = t; i < G_ * D_; i += 128) sm_q[i] = qs * qsrc[i];
        sm_bias[t] = bias[n * BS_ + t];
    }
    __syncthreads();

    const float* kbase = kcache + ((size_t)phys * BS_ * KVH_ + kv) * D_;
    const float* vbase = vcache + ((size_t)phys * BS_ * KVH_ + kv) * D_;
    float* redf = (float*)sm_red;

    // ================= QK phase =================
    // thread = (dc in 0..7: 16 d-elems at d = dc*4 + 32*i + j) x (sg in 0..15: 4 tokens)
    const int dc = t & 7;
    const int sg = t >> 3;

    // preload q for this thread's d-slice, all 4 heads: 4x4 ulonglong2 = 64 regs
    ulonglong2 qr[G_][4];
    #pragma unroll
    for (int h = 0; h < G_; ++h)
        #pragma unroll
        for (int i = 0; i < 4; ++i)
            qr[h][i] = *(const ulonglong2*)&sm_q[h * D_ + dc * 4 + 32 * i];

    #pragma unroll
    for (int pass = 0; pass < 2; ++pass) {
        const int sbase = pass * 64;

        unsigned long long acc[G_][4];
        #pragma unroll
        for (int h = 0; h < G_; ++h)
            #pragma unroll
            for (int sl = 0; sl < 4; ++sl) acc[h][sl] = 0ull;

        #pragma unroll
        for (int sl = 0; sl < 4; ++sl) {
            const float* krow = kbase + (size_t)(sbase + sg * 4 + sl) * (KVH_ * D_);
            ulonglong2 kk[4];
            #pragma unroll
            for (int i = 0; i < 4; ++i)
                kk[i] = *(const ulonglong2*)(krow + dc * 4 + 32 * i);
            #pragma unroll
            for (int h = 0; h < G_; ++h) {
                unsigned long long a = acc[h][sl];
                #pragma unroll
                for (int i = 0; i < 4; ++i) {
                    a = ffma2(kk[i].x, qr[h][i].x, a);
                    a = ffma2(kk[i].y, qr[h][i].y, a);
                }
                acc[h][sl] = a;
            }
        }

        __syncthreads();  // previous-pass readers of redf are done

        // fold f32x2 -> scalar partial, store redf[dc][h*64 + s64] (float4 per head)
        #pragma unroll
        for (int h = 0; h < G_; ++h) {
            float4 v4;
            float2 f0 = funpack2(acc[h][0]); v4.x = f0.x + f0.y;
            float2 f1 = funpack2(acc[h][1]); v4.y = f1.x + f1.y;
            float2 f2 = funpack2(acc[h][2]); v4.z = f2.x + f2.y;
            float2 f3 = funpack2(acc[h][3]); v4.w = f3.x + f3.y;
            *(float4*)&redf[dc * 256 + h * 64 + sg * 4] = v4;
        }
        __syncthreads();

        // reduce over dc, add bias, exp, store packed p, accumulate seq sums
        #pragma unroll
        for (int k2 = 0; k2 < 2; ++k2) {
            const int idx = t + 128 * k2;            // 0..255
            const int h   = idx >> 6;                // uniform per (warp, k2)
            const int s64 = idx & 63;
            float sc = 0.0f;
            #pragma unroll
            for (int dcc = 0; dcc < 8; ++dcc) sc += redf[dcc * 256 + h * 64 + s64];
            const float p = __expf(sc + sm_bias[sbase + s64] - CONSTV_);
            sm_pp[h * BS_ + sbase + s64] = fpack2(p, p);
            // warp-sum of p (all lanes same h) -> one global atomic per warp
            float ps = p;
            #pragma unroll
            for (int o = 16; o; o >>= 1) ps += __shfl_xor_sync(0xffffffffu, ps, o);
            if ((t & 31) == 0) atomicAdd(&g_seqsum[b * QH_ + kv * G_ + h], ps);
        }
    }
    __syncthreads();   // sm_pp complete; redf free for PV reuse

    // ================= PV phase =================
    // thread = (dg in 0..15: d = dg*4..dg*4+3 and 64+dg*4..+3) x (sg2 in 0..7: 16 tokens)
    const int dg  = t & 15;
    const int sg2 = t >> 4;

    unsigned long long o2[G_][4];
    #pragma unroll
    for (int h = 0; h < G_; ++h)
        #pragma unroll
        for (int j = 0; j < 4; ++j) o2[h][j] = 0ull;

    #pragma unroll 4
    for (int ss = 0; ss < 16; ++ss) {
        const int s = sg2 * 16 + ss;
        const float* vr = vbase + (size_t)s * (KVH_ * D_);
        ulonglong2 vlo = *(const ulonglong2*)(vr + dg * 4);        // d = dg*4 .. +3
        ulonglong2 vhi = *(const ulonglong2*)(vr + 64 + dg * 4);   // d = 64+dg*4 .. +3
        #pragma unroll
        for (int h = 0; h < G_; ++h) {
            const unsigned long long pp = sm_pp[h * BS_ + s];
            o2[h][0] = ffma2(vlo.x, pp, o2[h][0]);
            o2[h][1] = ffma2(vlo.y, pp, o2[h][1]);
            o2[h][2] = ffma2(vhi.x, pp, o2[h][2]);
            o2[h][3] = ffma2(vhi.y, pp, o2[h][3]);
        }
    }

    // write partials: sm_red[(sg2*4 + h)*64 + pr], pr = d/2
    #pragma unroll
    for (int h = 0; h < G_; ++h) {
        ulonglong2 w0; w0.x = o2[h][0]; w0.y = o2[h][1];
        ulonglong2 w1; w1.x = o2[h][2]; w1.y = o2[h][3];
        *(ulonglong2*)&sm_red[(sg2 * 4 + h) * 64 + dg * 2]      = w0;
        *(ulonglong2*)&sm_red[(sg2 * 4 + h) * 64 + 32 + dg * 2] = w1;
    }
    __syncthreads();

    // reduce over sg2 (8 partials), scale by mval, atomic-accumulate into out
    #pragma unroll
    for (int k2 = 0; k2 < 2; ++k2) {
        const int idx = t + 128 * k2;        // 0..255 -> (h, d-pair)
        const int h   = idx >> 6;
        const int pr  = idx & 63;
        unsigned long long sum = sm_red[h * 64 + pr];
        #pragma unroll
        for (int g2 = 1; g2 < 8; ++g2)
            sum = fadd2(sum, sm_red[(g2 * 4 + h) * 64 + pr]);
        float2 f = funpack2(sum);
        float* op = out + (size_t)b * QH_ * D_ + (size_t)(kv * G_ + h) * D_ + pr * 2;
        atomicAdd(op,     f.x * mval);
        atomicAdd(op + 1, f.y * mval);
    }
}

// ---- normalize: divide by (per-sequence exp sum + EPS) ----
__global__ void pa_norm(float* __restrict__ out) {
    int i = blockIdx.x * 256 + threadIdx.x;     // 512 x 256 == 131072 exactly
    out[i] = out[i] / (g_seqsum[i >> 7] + EPS_);
}

extern "C" void kernel_launch(void* const* d_in, const int* in_sizes, int n_in,
                              void* d_out, int out_size) {
    const float* query   = (const float*)d_in[0];
    const float* kcache  = (const float*)d_in[1];
    const float* vcache  = (const float*)d_in[2];
    const float* mapping = (const float*)d_in[3];
    const float* bias    = (const float*)d_in[4];
    const int*   blist   = (const int*)d_in[5];
    float* out = (float*)d_out;

    pa_init<<<512, 256>>>(out);
    pa_main<<<NB_ * KVH_, 128>>>(query, kcache, vcache, mapping, bias, blist, out);
    pa_norm<<<512, 256>>>(out);
}

// round 6
// speedup vs baseline: 1.0222x; 1.0222x over previous
#include <cuda_runtime.h>

// Problem constants (fixed shapes from reference)
#define NB_   512
#define B_    32
#define QH_   32
#define KVH_  8
#define G_    4          // GQA group: QH/KVH
#define D_    128
#define BS_   128
#define BPS_  16         // blocks per sequence
#define SCALE_ 0.08838834764831845f
#define CONSTV_ 10.0f
#define EPS_  1.1754943508222875e-38f

// Scratch: per-block partial outputs and per-block exp-sums (no atomics, no init needed:
// fully overwritten by pa_main before pa_norm reads them, every launch).
static __device__ float g_pout[NB_ * KVH_ * G_ * D_];   // 8 MB
static __device__ float g_bsum[NB_ * KVH_ * G_];        // 16 K floats

// ---- packed f32x2 helpers (Blackwell FFMA2 path) ----
__device__ __forceinline__ unsigned long long ffma2(unsigned long long a, unsigned long long b, unsigned long long c) {
    unsigned long long d;
    asm("fma.rn.f32x2 %0, %1, %2, %3;" : "=l"(d) : "l"(a), "l"(b), "l"(c));
    return d;
}
__device__ __forceinline__ unsigned long long fadd2(unsigned long long a, unsigned long long b) {
    unsigned long long d;
    asm("add.rn.f32x2 %0, %1, %2;" : "=l"(d) : "l"(a), "l"(b));
    return d;
}
__device__ __forceinline__ unsigned long long fpack2(float lo, float hi) {
    unsigned long long r;
    asm("mov.b64 %0, {%1, %2};" : "=l"(r) : "f"(lo), "f"(hi));
    return r;
}
__device__ __forceinline__ float2 funpack2(unsigned long long v) {
    float lo, hi;
    asm("mov.b64 {%0, %1}, %2;" : "=f"(lo), "=f"(hi) : "l"(v));
    return make_float2(lo, hi);
}

#define REDF_STRIDE 260   // 256 + 4 pad: breaks 8-way smem bank conflict across dc

// ---- main: one CTA per (block n, kv head). 128 threads, 4 CTAs/SM target. ----
__global__ void __launch_bounds__(128, 4) pa_main(
    const float* __restrict__ query,        // [B, QH, D]
    const float* __restrict__ kcache,       // [NCB, BS, KVH, D]
    const float* __restrict__ vcache,       // [NCB, BS, KVH, D]
    const float* __restrict__ mapping,      // [NB, B] one-hot
    const float* __restrict__ bias,         // [NB, BS]
    const int*   __restrict__ blist)        // [NB]
{
    __shared__ float sm_q[G_ * D_];                 // scaled q, 4 heads
    __shared__ float sm_bias[BS_];
    __shared__ unsigned long long sm_pp[G_ * BS_];  // exp(p) duplicated as (p,p) f32x2
    __shared__ unsigned long long sm_red[2080];     // union scratch: QK floats (8x260), PV u64 (2048)
    __shared__ float sm_hsum[G_];
    __shared__ int   sm_b;
    __shared__ float sm_m;

    const int t  = threadIdx.x;
    const int n  = blockIdx.x >> 3;
    const int kv = blockIdx.x & 7;

    // find batch index from one-hot mapping row (warp 0)
    if (t < 32) {
        float m = mapping[n * B_ + t];
        unsigned msk = __ballot_sync(0xffffffffu, m > 0.5f);
        int bb = __ffs(msk) - 1;
        float mv = __shfl_sync(0xffffffffu, m, bb);
        if (t == 0) { sm_b = bb; sm_m = mv; }
    }
    if (t < G_) sm_hsum[t] = 0.0f;
    __syncthreads();
    const int   b    = sm_b;
    const float mval = sm_m;
    const int   phys = blist[n];

    // stage scaled q (4 heads contiguous) + bias
    {
        const float qs = SCALE_ * mval;
        const float* qsrc = query + (size_t)b * QH_ * D_ + (size_t)kv * G_ * D_;
        #pragma unroll
        for (int i = t; i < G_ * D_; i += 128) sm_q[i] = qs * qsrc[i];
        sm_bias[t] = bias[n * BS_ + t];
    }

    const float* kbase = kcache + ((size_t)phys * BS_ * KVH_ + kv) * D_;
    const float* vbase = vcache + ((size_t)phys * BS_ * KVH_ + kv) * D_;
    float* redf = (float*)sm_red;

    // ================= QK phase =================
    // thread = (dc 0..7: 16 d-elems at d = dc*4 + 32*i + j) x (sg 0..15: 4 tokens)
    const int dc = t & 7;
    const int sg = t >> 3;

    __syncthreads();   // sm_q / sm_bias ready

    // preload q for this thread's d-slice, all 4 heads
    ulonglong2 qr[G_][4];
    #pragma unroll
    for (int h = 0; h < G_; ++h)
        #pragma unroll
        for (int i = 0; i < 4; ++i)
            qr[h][i] = *(const ulonglong2*)&sm_q[h * D_ + dc * 4 + 32 * i];

    #pragma unroll
    for (int pass = 0; pass < 2; ++pass) {
        const int sbase = pass * 64;

        if (pass) __syncthreads();   // protect redf from previous pass's readers

        #pragma unroll
        for (int sl = 0; sl < 4; ++sl) {
            const float* krow = kbase + (size_t)(sbase + sg * 4 + sl) * (KVH_ * D_);
            ulonglong2 kk[4];
            #pragma unroll
            for (int i = 0; i < 4; ++i)
                kk[i] = *(const ulonglong2*)(krow + dc * 4 + 32 * i);
            #pragma unroll
            for (int h = 0; h < G_; ++h) {
                unsigned long long a = 0ull;
                #pragma unroll
                for (int i = 0; i < 4; ++i) {
                    a = ffma2(kk[i].x, qr[h][i].x, a);
                    a = ffma2(kk[i].y, qr[h][i].y, a);
                }
                float2 f = funpack2(a);
                redf[dc * REDF_STRIDE + h * 64 + sg * 4 + sl] = f.x + f.y;
            }
        }
        __syncthreads();

        // reduce over dc, add bias, exp, store packed p, accumulate head sums
        #pragma unroll
        for (int k2 = 0; k2 < 2; ++k2) {
            const int idx = t + 128 * k2;            // 0..255
            const int h   = idx >> 6;                // uniform per (warp, k2)
            const int s64 = idx & 63;
            float sc = 0.0f;
            #pragma unroll
            for (int dcc = 0; dcc < 8; ++dcc) sc += redf[dcc * REDF_STRIDE + h * 64 + s64];
            const float p = __expf(sc + sm_bias[sbase + s64] - CONSTV_);
            sm_pp[h * BS_ + sbase + s64] = fpack2(p, p);
            float ps = p;
            #pragma unroll
            for (int o = 16; o; o >>= 1) ps += __shfl_xor_sync(0xffffffffu, ps, o);
            if ((t & 31) == 0) atomicAdd(&sm_hsum[h], ps);
        }
    }
    __syncthreads();   // sm_pp + sm_hsum complete; redf free for PV reuse

    // per-block exp sums -> scratch (plain store, no global atomics)
    if (t < G_) g_bsum[(n * KVH_ + kv) * G_ + t] = sm_hsum[t];

    // ================= PV phase =================
    // thread = (dg 0..15: d = dg*4..+3 and 64+dg*4..+3) x (sg2 0..7: 16 tokens)
    const int dg  = t & 15;
    const int sg2 = t >> 4;

    unsigned long long o2[G_][4];
    #pragma unroll
    for (int h = 0; h < G_; ++h)
        #pragma unroll
        for (int j = 0; j < 4; ++j) o2[h][j] = 0ull;

    #pragma unroll 8
    for (int ss = 0; ss < 16; ++ss) {
        const int s = sg2 * 16 + ss;
        const float* vr = vbase + (size_t)s * (KVH_ * D_);
        ulonglong2 vlo = *(const ulonglong2*)(vr + dg * 4);
        ulonglong2 vhi = *(const ulonglong2*)(vr + 64 + dg * 4);
        #pragma unroll
        for (int h = 0; h < G_; ++h) {
            const unsigned long long pp = sm_pp[h * BS_ + s];
            o2[h][0] = ffma2(vlo.x, pp, o2[h][0]);
            o2[h][1] = ffma2(vlo.y, pp, o2[h][1]);
            o2[h][2] = ffma2(vhi.x, pp, o2[h][2]);
            o2[h][3] = ffma2(vhi.y, pp, o2[h][3]);
        }
    }

    // write partials: sm_red[(sg2*4 + h)*64 + pr], pr = d/2
    #pragma unroll
    for (int h = 0; h < G_; ++h) {
        ulonglong2 w0; w0.x = o2[h][0]; w0.y = o2[h][1];
        ulonglong2 w1; w1.x = o2[h][2]; w1.y = o2[h][3];
        *(ulonglong2*)&sm_red[(sg2 * 4 + h) * 64 + dg * 2]      = w0;
        *(ulonglong2*)&sm_red[(sg2 * 4 + h) * 64 + 32 + dg * 2] = w1;
    }
    __syncthreads();

    // reduce over sg2 (8 partials), scale by mval, coalesced store to scratch
    #pragma unroll
    for (int k2 = 0; k2 < 2; ++k2) {
        const int idx = t + 128 * k2;        // 0..255 -> (h, d-pair)
        const int h   = idx >> 6;
        const int pr  = idx & 63;
        unsigned long long sum = sm_red[h * 64 + pr];
        #pragma unroll
        for (int g2 = 1; g2 < 8; ++g2)
            sum = fadd2(sum, sm_red[(g2 * 4 + h) * 64 + pr]);
        float2 f = funpack2(sum);
        float2 w = make_float2(f.x * mval, f.y * mval);
        *(float2*)&g_pout[((size_t)(n * KVH_ + kv) * G_ + h) * D_ + pr * 2] = w;
    }
}

// ---- norm+reduce: sum 16 block partials per sequence, divide by seq exp-sum ----
__global__ void pa_norm(float* __restrict__ out) {
    const int i  = blockIdx.x * 256 + threadIdx.x;   // 512 x 256 == 131072 exactly
    const int d  = i & 127;
    const int qh = (i >> 7) & 31;
    const int b  = i >> 12;
    const int kv = qh >> 2;
    const int h  = qh & 3;

    const float* pb = g_pout + (size_t)b * BPS_ * KVH_ * G_ * D_ + (size_t)(kv * G_ + h) * D_ + d;
    const float* sb = g_bsum + b * BPS_ * KVH_ * G_ + kv * G_ + h;
    float acc = 0.0f, s = 0.0f;
    #pragma unroll
    for (int j = 0; j < BPS_; ++j) {
        acc += pb[(size_t)j * (KVH_ * G_ * D_)];
        s   += sb[j * (KVH_ * G_)];
    }
    out[i] = acc / (s + EPS_);
}

extern "C" void kernel_launch(void* const* d_in, const int* in_sizes, int n_in,
                              void* d_out, int out_size) {
    const float* query   = (const float*)d_in[0];
    const float* kcache  = (const float*)d_in[1];
    const float* vcache  = (const float*)d_in[2];
    const float* mapping = (const float*)d_in[3];
    const float* bias    = (const float*)d_in[4];
    const int*   blist   = (const int*)d_in[5];
    float* out = (float*)d_out;

    pa_main<<<NB_ * KVH_, 128>>>(query, kcache, vcache, mapping, bias, blist);
    pa_norm<<<512, 256>>>(out);
}

// round 10
// speedup vs baseline: 1.0247x; 1.0024x over previous
#include <cuda_runtime.h>

// Problem constants (fixed shapes from reference)
#define NB_   512
#define B_    32
#define QH_   32
#define KVH_  8
#define G_    4          // GQA group: QH/KVH
#define D_    128
#define BS_   128
#define BPS_  16         // blocks per sequence
#define SCALE_ 0.08838834764831845f
#define CONSTV_ 10.0f
#define EPS_  1.1754943508222875e-38f

// Scratch: per-block partial outputs and per-block exp-sums (no atomics; fully
// overwritten by pa_main before pa_norm reads them, every launch).
static __device__ float g_pout[NB_ * KVH_ * G_ * D_];   // 8 MB
static __device__ float g_bsum[NB_ * KVH_ * G_];        // 16 K floats

// ---- packed f32x2 helpers (Blackwell FFMA2 path) ----
__device__ __forceinline__ unsigned long long ffma2(unsigned long long a, unsigned long long b, unsigned long long c) {
    unsigned long long d;
    asm("fma.rn.f32x2 %0, %1, %2, %3;" : "=l"(d) : "l"(a), "l"(b), "l"(c));
    return d;
}
__device__ __forceinline__ unsigned long long fadd2(unsigned long long a, unsigned long long b) {
    unsigned long long d;
    asm("add.rn.f32x2 %0, %1, %2;" : "=l"(d) : "l"(a), "l"(b));
    return d;
}
__device__ __forceinline__ unsigned long long fpack2(float lo, float hi) {
    unsigned long long r;
    asm("mov.b64 %0, {%1, %2};" : "=l"(r) : "f"(lo), "f"(hi));
    return r;
}
__device__ __forceinline__ float2 funpack2(unsigned long long v) {
    float lo, hi;
    asm("mov.b64 {%0, %1}, %2;" : "=f"(lo), "=f"(hi) : "l"(v));
    return make_float2(lo, hi);
}
// streaming (evict-first) 16B load via compiler intrinsic
__device__ __forceinline__ ulonglong2 ldcs128(const float* p) {
    uint4 v = __ldcs((const uint4*)p);
    ulonglong2 r;
    r.x = ((unsigned long long)v.y << 32) | v.x;
    r.y = ((unsigned long long)v.w << 32) | v.z;
    return r;
}

#define REDF_STRIDE 257   // odd stride: store conflict degree 4 -> 2, reads stay conflict-free

// ---- main: one CTA per (block n, kv head). 128 threads, 4 CTAs/SM. ----
__global__ void __launch_bounds__(128, 4) pa_main(
    const float* __restrict__ query,        // [B, QH, D]
    const float* __restrict__ kcache,       // [NCB, BS, KVH, D]
    const float* __restrict__ vcache,       // [NCB, BS, KVH, D]
    const float* __restrict__ mapping,      // [NB, B] one-hot
    const float* __restrict__ bias,         // [NB, BS]
    const int*   __restrict__ blist)        // [NB]
{
    __shared__ float sm_q[G_ * D_];                 // scaled q, 4 heads
    __shared__ float sm_bias[BS_];
    __shared__ unsigned long long sm_pp[G_ * BS_];  // exp(p) duplicated as (p,p) f32x2
    __shared__ unsigned long long sm_red[2080];     // union scratch: QK floats (8x257), PV u64 (2048)
    __shared__ float sm_hsum[G_];
    __shared__ int   sm_b;
    __shared__ float sm_m;

    const int t  = threadIdx.x;
    const int n  = blockIdx.x >> 3;
    const int kv = blockIdx.x & 7;

    // find batch index from one-hot mapping row (warp 0)
    if (t < 32) {
        float m = mapping[n * B_ + t];
        unsigned msk = __ballot_sync(0xffffffffu, m > 0.5f);
        int bb = __ffs(msk) - 1;
        float mv = __shfl_sync(0xffffffffu, m, bb);
        if (t == 0) { sm_b = bb; sm_m = mv; }
    }
    if (t < G_) sm_hsum[t] = 0.0f;
    __syncthreads();
    const int   b    = sm_b;
    const float mval = sm_m;
    const int   phys = blist[n];

    // stage scaled q (4 heads contiguous) + bias
    {
        const float qs = SCALE_ * mval;
        const float* qsrc = query + (size_t)b * QH_ * D_ + (size_t)kv * G_ * D_;
        #pragma unroll
        for (int i = t; i < G_ * D_; i += 128) sm_q[i] = qs * qsrc[i];
        sm_bias[t] = bias[n * BS_ + t];
    }

    const float* kbase = kcache + ((size_t)phys * BS_ * KVH_ + kv) * D_;
    const float* vbase = vcache + ((size_t)phys * BS_ * KVH_ + kv) * D_;
    float* redf = (float*)sm_red;

    // ================= QK phase =================
    // thread = (dc 0..7: 16 d-elems at d = dc*4 + 32*i + j) x (sg 0..15: 4 tokens)
    const int dc = t & 7;
    const int sg = t >> 3;

    __syncthreads();   // sm_q / sm_bias ready

    // preload q for this thread's d-slice, all 4 heads
    ulonglong2 qr[G_][4];
    #pragma unroll
    for (int h = 0; h < G_; ++h)
        #pragma unroll
        for (int i = 0; i < 4; ++i)
            qr[h][i] = *(const ulonglong2*)&sm_q[h * D_ + dc * 4 + 32 * i];

    #pragma unroll
    for (int pass = 0; pass < 2; ++pass) {
        const int sbase = pass * 64;

        if (pass) __syncthreads();   // protect redf from previous pass's readers

        #pragma unroll
        for (int sl = 0; sl < 4; ++sl) {
            const float* krow = kbase + (size_t)(sbase + sg * 4 + sl) * (KVH_ * D_);
            ulonglong2 kk[4];
            #pragma unroll
            for (int i = 0; i < 4; ++i)
                kk[i] = ldcs128(krow + dc * 4 + 32 * i);
            #pragma unroll
            for (int h = 0; h < G_; ++h) {
                unsigned long long a = 0ull;
                #pragma unroll
                for (int i = 0; i < 4; ++i) {
                    a = ffma2(kk[i].x, qr[h][i].x, a);
                    a = ffma2(kk[i].y, qr[h][i].y, a);
                }
                float2 f = funpack2(a);
                redf[dc * REDF_STRIDE + h * 64 + sg * 4 + sl] = f.x + f.y;
            }
        }
        __syncthreads();

        // reduce over dc, add bias, exp, store packed p, accumulate head sums
        #pragma unroll
        for (int k2 = 0; k2 < 2; ++k2) {
            const int idx = t + 128 * k2;            // 0..255
            const int h   = idx >> 6;                // uniform per (warp, k2)
            const int s64 = idx & 63;
            float sc = 0.0f;
            #pragma unroll
            for (int dcc = 0; dcc < 8; ++dcc) sc += redf[dcc * REDF_STRIDE + h * 64 + s64];
            const float p = __expf(sc + sm_bias[sbase + s64] - CONSTV_);
            sm_pp[h * BS_ + sbase + s64] = fpack2(p, p);
            float ps = p;
            #pragma unroll
            for (int o = 16; o; o >>= 1) ps += __shfl_xor_sync(0xffffffffu, ps, o);
            if ((t & 31) == 0) atomicAdd(&sm_hsum[h], ps);
        }
    }

    // ================= PV phase =================
    // thread = (dg 0..15: d = dg*4..+3 and 64+dg*4..+3) x (sg2 0..7: 16 tokens)
    const int dg  = t & 15;
    const int sg2 = t >> 4;

    // prefetch first 2 V rows BEFORE the phase sync (register-only, no hazard):
    // hides DRAM latency across the QK->PV boundary
    ulonglong2 pvlo[2], pvhi[2];
    #pragma unroll
    for (int pf = 0; pf < 2; ++pf) {
        const float* vr = vbase + (size_t)(sg2 * 16 + pf) * (KVH_ * D_);
        pvlo[pf] = ldcs128(vr + dg * 4);
        pvhi[pf] = ldcs128(vr + 64 + dg * 4);
    }

    __syncthreads();   // sm_pp + sm_hsum complete; redf free for PV reuse

    // per-block exp sums -> scratch (plain store, no global atomics)
    if (t < G_) g_bsum[(n * KVH_ + kv) * G_ + t] = sm_hsum[t];

    unsigned long long o2[G_][4];
    #pragma unroll
    for (int h = 0; h < G_; ++h)
        #pragma unroll
        for (int j = 0; j < 4; ++j) o2[h][j] = 0ull;

    // peeled: prefetched rows
    #pragma unroll
    for (int ss = 0; ss < 2; ++ss) {
        const int s = sg2 * 16 + ss;
        #pragma unroll
        for (int h = 0; h < G_; ++h) {
            const unsigned long long pp = sm_pp[h * BS_ + s];
            o2[h][0] = ffma2(pvlo[ss].x, pp, o2[h][0]);
            o2[h][1] = ffma2(pvlo[ss].y, pp, o2[h][1]);
            o2[h][2] = ffma2(pvhi[ss].x, pp, o2[h][2]);
            o2[h][3] = ffma2(pvhi[ss].y, pp, o2[h][3]);
        }
    }
    #pragma unroll 7
    for (int ss = 2; ss < 16; ++ss) {
        const int s = sg2 * 16 + ss;
        const float* vr = vbase + (size_t)s * (KVH_ * D_);
        ulonglong2 vlo = ldcs128(vr + dg * 4);
        ulonglong2 vhi = ldcs128(vr + 64 + dg * 4);
        #pragma unroll
        for (int h = 0; h < G_; ++h) {
            const unsigned long long pp = sm_pp[h * BS_ + s];
            o2[h][0] = ffma2(vlo.x, pp, o2[h][0]);
            o2[h][1] = ffma2(vlo.y, pp, o2[h][1]);
            o2[h][2] = ffma2(vhi.x, pp, o2[h][2]);
            o2[h][3] = ffma2(vhi.y, pp, o2[h][3]);
        }
    }

    // write partials: sm_red[(sg2*4 + h)*64 + pr], pr = d/2
    #pragma unroll
    for (int h = 0; h < G_; ++h) {
        ulonglong2 w0; w0.x = o2[h][0]; w0.y = o2[h][1];
        ulonglong2 w1; w1.x = o2[h][2]; w1.y = o2[h][3];
        *(ulonglong2*)&sm_red[(sg2 * 4 + h) * 64 + dg * 2]      = w0;
        *(ulonglong2*)&sm_red[(sg2 * 4 + h) * 64 + 32 + dg * 2] = w1;
    }
    __syncthreads();

    // reduce over sg2 (8 partials), scale by mval, coalesced store to scratch
    #pragma unroll
    for (int k2 = 0; k2 < 2; ++k2) {
        const int idx = t + 128 * k2;        // 0..255 -> (h, d-pair)
        const int h   = idx >> 6;
        const int pr  = idx & 63;
        unsigned long long sum = sm_red[h * 64 + pr];
        #pragma unroll
        for (int g2 = 1; g2 < 8; ++g2)
            sum = fadd2(sum, sm_red[(g2 * 4 + h) * 64 + pr]);
        float2 f = funpack2(sum);
        float2 w = make_float2(f.x * mval, f.y * mval);
        *(float2*)&g_pout[((size_t)(n * KVH_ + kv) * G_ + h) * D_ + pr * 2] = w;
    }
}

// ---- norm+reduce: sum 16 block partials per sequence, divide by seq exp-sum.
//      float4-vectorized: thread i handles 4 consecutive d values. ----
__global__ void __launch_bounds__(128) pa_norm(float* __restrict__ out) {
    const int i4 = blockIdx.x * 128 + threadIdx.x;   // 256 x 128 = 32768 float4s exactly
    const int d4 = i4 & 31;            // float4 index within head dim
    const int qh = (i4 >> 5) & 31;
    const int b  = i4 >> 10;
    const int kv = qh >> 2;
    const int h  = qh & 3;

    const float4* pb = (const float4*)(g_pout
        + (size_t)b * BPS_ * KVH_ * G_ * D_ + (size_t)(kv * G_ + h) * D_) + d4;
    const float* sb = g_bsum + b * BPS_ * KVH_ * G_ + kv * G_ + h;

    float4 acc = make_float4(0.f, 0.f, 0.f, 0.f);
    float s = 0.0f;
    #pragma unroll
    for (int j = 0; j < BPS_; ++j) {
        float4 v = pb[(size_t)j * (KVH_ * G_ * D_ / 4)];
        acc.x += v.x; acc.y += v.y; acc.z += v.z; acc.w += v.w;
        s += sb[j * (KVH_ * G_)];
    }
    const float inv = 1.0f / (s + EPS_);
    float4 r = make_float4(acc.x * inv, acc.y * inv, acc.z * inv, acc.w * inv);
    ((float4*)out)[i4] = r;
}

extern "C" void kernel_launch(void* const* d_in, const int* in_sizes, int n_in,
                              void* d_out, int out_size) {
    const float* query   = (const float*)d_in[0];
    const float* kcache  = (const float*)d_in[1];
    const float* vcache  = (const float*)d_in[2];
    const float* mapping = (const float*)d_in[3];
    const float* bias    = (const float*)d_in[4];
    const int*   blist   = (const int*)d_in[5];
    float* out = (float*)d_out;

    pa_main<<<NB_ * KVH_, 128>>>(query, kcache, vcache, mapping, bias, blist);
    pa_norm<<<256, 128>>>(out);
}